// round 13
// baseline (speedup 1.0000x reference)
#include <cuda_runtime.h>
#include <cstdint>

#define Mdim 8192
#define Ndim 8192
#define Kdim 256
#define SAEK 32
#define CCAP 512
#define TCOEF 0.145f     // 2.32 sigma / 16  (gate at 2.48 sigma, ~3 sd below 32nd OS)
#define ECOEF 0.0100f    // int8 screening-error bound (abs / ||x||)

// ---------------- device scratch ----------------
__device__ uint32_t g_x8[(size_t)Mdim * Kdim / 4];   // int8 packed (x - b_dec)
__device__ uint32_t g_w8[(size_t)Ndim * Kdim / 4];   // int8 packed W_enc
__device__ float    g_rnorm[Mdim];
__device__ float    g_sx[Mdim],  g_isx[Mdim];
__device__ float    g_sw[Ndim],  g_isw[Ndim];
__device__ int      g_ccnt[Mdim];
__device__ int      g_cand_col[(size_t)Mdim * CCAP];
__device__ float    g_fbrow[(size_t)Mdim * Ndim];    // dense-fallback scratch (cold)

// ---------------- portable PTX helpers ----------------
__device__ __forceinline__ uint32_t smem_u32(const void* p) {
    uint32_t a;
    asm("{ .reg .u64 t; cvta.to.shared.u64 t, %1; cvt.u32.u64 %0, t; }" : "=r"(a) : "l"(p));
    return a;
}
__device__ __forceinline__ void cp_async16(uint32_t s, const void* g) {
    asm volatile("cp.async.cg.shared.global [%0], [%1], 16;" :: "r"(s), "l"(g));
}
#define CP_COMMIT() asm volatile("cp.async.commit_group;" ::: "memory")

#define LDSM_X4(r0,r1,r2,r3,addr) \
    asm volatile("ldmatrix.sync.aligned.m8n8.x4.shared.b16 {%0,%1,%2,%3}, [%4];" \
        : "=r"(r0),"=r"(r1),"=r"(r2),"=r"(r3) : "r"(addr))
#define MMA_S8(d,a,b) \
    asm volatile("mma.sync.aligned.m16n8k32.row.col.s32.s8.s8.s32 " \
        "{%0,%1,%2,%3},{%4,%5,%6,%7},{%8,%9},{%0,%1,%2,%3};" \
        : "+r"((d)[0]),"+r"((d)[1]),"+r"((d)[2]),"+r"((d)[3]) \
        : "r"((a)[0]),"r"((a)[1]),"r"((a)[2]),"r"((a)[3]),"r"((b)[0]),"r"((b)[1]))

// ---------------------------------------------------------------------------
// Kernel: per-row stats + candidate-counter zeroing. One warp per row.
// ---------------------------------------------------------------------------
__global__ __launch_bounds__(256)
void stats_kernel(const float* __restrict__ x, const float* __restrict__ Wenc,
                  const float* __restrict__ b_dec)
{
    const int wid = threadIdx.x >> 5, lane = threadIdx.x & 31;
    const int row = blockIdx.x * 8 + wid;
    if (row < Mdim) {
        const float* xr = x + (size_t)row * Kdim + lane * 8;
        float s = 0.f, mx = 0.f;
#pragma unroll
        for (int j = 0; j < 8; j++) {
            float e = xr[j] - __ldg(b_dec + lane * 8 + j);
            s = fmaf(e, e, s);
            mx = fmaxf(mx, fabsf(e));
        }
#pragma unroll
        for (int o = 16; o; o >>= 1) {
            s  += __shfl_down_sync(0xFFFFFFFFu, s, o);
            mx = fmaxf(mx, __shfl_down_sync(0xFFFFFFFFu, mx, o));
        }
        if (lane == 0) {
            g_rnorm[row] = sqrtf(s);
            g_sx[row]  = mx * (1.f / 127.f);
            g_isx[row] = (mx > 0.f) ? (127.f / mx) : 0.f;
            g_ccnt[row] = 0;
        }
    } else {
        const int r = row - Mdim;
        const float* wr = Wenc + (size_t)r * Kdim + lane * 8;
        float mx = 0.f;
#pragma unroll
        for (int j = 0; j < 8; j++) mx = fmaxf(mx, fabsf(wr[j]));
#pragma unroll
        for (int o = 16; o; o >>= 1) mx = fmaxf(mx, __shfl_down_sync(0xFFFFFFFFu, mx, o));
        if (lane == 0) {
            g_sw[r]  = mx * (1.f / 127.f);
            g_isw[r] = (mx > 0.f) ? (127.f / mx) : 0.f;
        }
    }
}

// ---------------------------------------------------------------------------
// Kernel: quantize (x - b_dec) and W_enc to int8 (16 elements / thread)
// ---------------------------------------------------------------------------
__device__ __forceinline__ uint32_t q4(const float* v, float inv) {
    int q0 = max(-127, min(127, __float2int_rn(v[0] * inv)));
    int q1 = max(-127, min(127, __float2int_rn(v[1] * inv)));
    int q2 = max(-127, min(127, __float2int_rn(v[2] * inv)));
    int q3 = max(-127, min(127, __float2int_rn(v[3] * inv)));
    return (uint32_t)(q0 & 255) | ((uint32_t)(q1 & 255) << 8) |
           ((uint32_t)(q2 & 255) << 16) | ((uint32_t)(q3 & 255) << 24);
}

__global__ __launch_bounds__(256)
void prep_pack_s8(const float* __restrict__ x, const float* __restrict__ Wenc,
                  const float* __restrict__ b_dec)
{
    const size_t XT = (size_t)Mdim * Kdim / 16;
    size_t i = (size_t)blockIdx.x * 256 + threadIdx.x;
    float v[16];
    float inv;
    uint32_t* dst;
    if (i < XT) {
        const size_t base = i * 16;
        const int row = (int)(base >> 8);
        const int k = (int)(base & (Kdim - 1));
        inv = __ldg(g_isx + row);
#pragma unroll
        for (int j = 0; j < 16; j += 4) {
            float4 a = *(const float4*)(x + base + j);
            v[j]   = a.x - __ldg(b_dec + k + j);
            v[j+1] = a.y - __ldg(b_dec + k + j + 1);
            v[j+2] = a.z - __ldg(b_dec + k + j + 2);
            v[j+3] = a.w - __ldg(b_dec + k + j + 3);
        }
        dst = g_x8 + i * 4;
    } else {
        const size_t base = (i - XT) * 16;
        const int row = (int)(base >> 8);
        inv = __ldg(g_isw + row);
#pragma unroll
        for (int j = 0; j < 16; j += 4) {
            float4 a = *(const float4*)(Wenc + base + j);
            v[j] = a.x; v[j+1] = a.y; v[j+2] = a.z; v[j+3] = a.w;
        }
        dst = g_w8 + (i - XT) * 4;
    }
    uint4 o;
    o.x = q4(v + 0,  inv);
    o.y = q4(v + 4,  inv);
    o.z = q4(v + 8,  inv);
    o.w = q4(v + 12, inv);
    *(uint4*)dst = o;
}

// ---------------------------------------------------------------------------
// Kernel: int8 screening GEMM, 128x128 tile, BK=32, 3-stage cp.async,
// B fragments loaded pairwise via ldmatrix.x4 (6 LDSM per 16 mma).
// ---------------------------------------------------------------------------
#define SROW 48u
#define TILE8 (128u * SROW)      // 6144 B
#define STAGE8 (2u * TILE8)      // 12288 B

__global__ __launch_bounds__(256, 2)
void screen_gemm_s8(const float* __restrict__ b_enc)
{
    extern __shared__ char smc[];
    const uint32_t smb = smem_u32(smc);
    const int tid = threadIdx.x, lane = tid & 31, wid = tid >> 5;
    const int wm = wid & 1, wn = wid >> 1;
    const int m0 = blockIdx.y * 128, n0 = blockIdx.x * 128;

    int acc[4][4][4];
#pragma unroll
    for (int a = 0; a < 4; a++)
#pragma unroll
        for (int b = 0; b < 4; b++)
#pragma unroll
            for (int c = 0; c < 4; c++) acc[a][b][c] = 0;

    const int prow = tid >> 1;
    const int half = tid & 1;

    auto prefetch = [&](int c) {
        const uint32_t st = smb + (uint32_t)(c % 3) * STAGE8;
        const uint32_t da = st + (uint32_t)prow * SROW + (uint32_t)half * 16u;
        const char* ga = (const char*)g_x8 + (size_t)(m0 + prow) * Kdim + c * 32 + half * 16;
        const char* gb = (const char*)g_w8 + (size_t)(n0 + prow) * Kdim + c * 32 + half * 16;
        cp_async16(da,         ga);
        cp_async16(da + TILE8, gb);
        CP_COMMIT();
    };

    prefetch(0); prefetch(1);

    // B ldmatrix.x4 lane mapping: quad q = lane>>3; matrix q covers
    // (nt_local = q>>1, k-half = q&1); rows = lane&7.
    const int bq_nt = (lane >> 4) & 1;       // nt within pair
    const int bq_kh = (lane >> 3) & 1;       // k half
    const int brow  = lane & 7;

    for (int c = 0; c < 8; c++) {
        if (c < 7) asm volatile("cp.async.wait_group 1;" ::: "memory");
        else       asm volatile("cp.async.wait_group 0;" ::: "memory");
        __syncthreads();
        if (c + 2 < 8) prefetch(c + 2);

        const uint32_t sA = smb + (uint32_t)(c % 3) * STAGE8;
        const uint32_t sB = sA + TILE8;

        uint32_t af[4][4], bf[4][2];
#pragma unroll
        for (int mt = 0; mt < 4; mt++) {
            const uint32_t ad = sA + (uint32_t)(wm * 64 + mt * 16 + (lane & 15)) * SROW
                              + (uint32_t)((lane >> 4) * 16);
            LDSM_X4(af[mt][0], af[mt][1], af[mt][2], af[mt][3], ad);
        }
#pragma unroll
        for (int ntp = 0; ntp < 2; ntp++) {
            const uint32_t bd = sB + (uint32_t)(wn * 32 + (ntp * 2 + bq_nt) * 8 + brow) * SROW
                              + (uint32_t)(bq_kh * 16);
            LDSM_X4(bf[ntp * 2][0], bf[ntp * 2][1],
                    bf[ntp * 2 + 1][0], bf[ntp * 2 + 1][1], bd);
        }
#pragma unroll
        for (int mt = 0; mt < 4; mt++)
#pragma unroll
            for (int nt = 0; nt < 4; nt++)
                MMA_S8(acc[mt][nt], af[mt], bf[nt]);
    }

    // epilogue: dequant + threshold append
#pragma unroll
    for (int mt = 0; mt < 4; mt++) {
        const int r0 = m0 + wm * 64 + mt * 16 + (lane >> 2);
        const int r1 = r0 + 8;
        const float sx0 = __ldg(g_sx + r0), sx1 = __ldg(g_sx + r1);
        const float T0 = TCOEF * __ldg(g_rnorm + r0);
        const float T1 = TCOEF * __ldg(g_rnorm + r1);
#pragma unroll
        for (int nt = 0; nt < 4; nt++) {
            const int c0 = n0 + wn * 32 + nt * 8 + 2 * (lane & 3);
            const float sw0 = __ldg(g_sw + c0), sw1 = __ldg(g_sw + c0 + 1);
            const float be0 = __ldg(b_enc + c0), be1 = __ldg(b_enc + c0 + 1);
            float v0 = (float)acc[mt][nt][0] * (sx0 * sw0) + be0;
            float v1 = (float)acc[mt][nt][1] * (sx0 * sw1) + be1;
            float v2 = (float)acc[mt][nt][2] * (sx1 * sw0) + be0;
            float v3 = (float)acc[mt][nt][3] * (sx1 * sw1) + be1;
            if (v0 >= T0) { int p = atomicAdd(&g_ccnt[r0], 1); if (p < CCAP) g_cand_col[(size_t)r0 * CCAP + p] = c0; }
            if (v1 >= T0) { int p = atomicAdd(&g_ccnt[r0], 1); if (p < CCAP) g_cand_col[(size_t)r0 * CCAP + p] = c0 + 1; }
            if (v2 >= T1) { int p = atomicAdd(&g_ccnt[r1], 1); if (p < CCAP) g_cand_col[(size_t)r1 * CCAP + p] = c0; }
            if (v3 >= T1) { int p = atomicAdd(&g_ccnt[r1], 1); if (p < CCAP) g_cand_col[(size_t)r1 * CCAP + p] = c0 + 1; }
        }
    }
}

// ---------------------------------------------------------------------------
// Kernel: exact fp32 rescore (R7 shape: warp-per-candidate, cp.async dbuf)
//         + one-pass rank top-32 + fused decode.
// ---------------------------------------------------------------------------
__global__ __launch_bounds__(256)
void rescore_decode(const float* __restrict__ x, const float* __restrict__ Wenc,
                    const float* __restrict__ b_enc, const float* __restrict__ Wdec,
                    const float* __restrict__ b_dec, float* __restrict__ out)
{
    __shared__ float s_x[Kdim];
    __shared__ __align__(16) float s_w[8][2][Kdim];   // 16 KB candidate buffers
    __shared__ int   s_col[CCAP];
    __shared__ float s_val[CCAP];
    __shared__ float s_sel_v[SAEK];
    __shared__ int   s_sel_i[SAEK];
    __shared__ float s_rv[8];
    __shared__ int   s_ri[8];
    __shared__ int   s_fb;

    const int row = blockIdx.x;
    const int tid = threadIdx.x;
    const int wid = tid >> 5, lane = tid & 31;

    s_x[tid] = x[(size_t)row * Kdim + tid] - __ldg(b_dec + tid);
    if (tid == 0) s_fb = 0;
    __syncthreads();

    float xr[8];
#pragma unroll
    for (int j = 0; j < 8; j++) xr[j] = s_x[lane * 8 + j];

    const int n = g_ccnt[row];
    const float rn = g_rnorm[row];
    bool fb = (n < SAEK) || (n > CCAP);

    if (!fb) {
        for (int i = tid; i < n; i += 256) s_col[i] = g_cand_col[(size_t)row * CCAP + i];
        __syncthreads();

        // per-lane buffer addresses: lane writes & reads ITS OWN 32 bytes.
        const uint32_t wb0 = smem_u32(&s_w[wid][0][0]) + (uint32_t)lane * 32u;
        const uint32_t wb1 = smem_u32(&s_w[wid][1][0]) + (uint32_t)lane * 32u;

        {
            const char* src = (const char*)(Wenc + (size_t)s_col[wid] * Kdim) + lane * 32;
            cp_async16(wb0,      src);
            cp_async16(wb0 + 16, src + 16);
        }
        CP_COMMIT();

        int buf = 0;
        for (int c = wid; c < n; c += 8, buf ^= 1) {
            const int cn = c + 8;
            if (cn < n) {
                const uint32_t d = buf ? wb0 : wb1;
                const char* src = (const char*)(Wenc + (size_t)s_col[cn] * Kdim) + lane * 32;
                cp_async16(d,      src);
                cp_async16(d + 16, src + 16);
            }
            CP_COMMIT();
            asm volatile("cp.async.wait_group 1;" ::: "memory");

            const float* wr = &s_w[wid][buf][lane * 8];
            float4 w0 = *(const float4*)wr;
            float4 w1 = *(const float4*)(wr + 4);
            float s = xr[0] * w0.x;
            s = fmaf(xr[1], w0.y, s); s = fmaf(xr[2], w0.z, s); s = fmaf(xr[3], w0.w, s);
            s = fmaf(xr[4], w1.x, s); s = fmaf(xr[5], w1.y, s); s = fmaf(xr[6], w1.z, s);
            s = fmaf(xr[7], w1.w, s);
#pragma unroll
            for (int o = 16; o; o >>= 1) s += __shfl_xor_sync(0xFFFFFFFFu, s, o);
            if (lane == 0) s_val[c] = s + __ldg(b_enc + s_col[c]);
        }
        asm volatile("cp.async.wait_group 0;" ::: "memory");
        __syncthreads();

        // one-pass rank selection (keys unique: (val desc, col asc))
        for (int i = tid; i < n; i += 256) {
            const float vi = s_val[i];
            const int   ci = s_col[i];
            int r = 0;
            for (int j = 0; j < n; j++) {
                const float vj = s_val[j];
                r += (vj > vi) || (vj == vi && s_col[j] < ci);
            }
            if (r < SAEK) { s_sel_v[r] = vi; s_sel_i[r] = ci; }
        }
        __syncthreads();

        // validity gate
        if (tid == 0 && s_sel_v[SAEK - 1] < (TCOEF + ECOEF) * rn + 1e-6f) s_fb = 1;
        __syncthreads();
        fb = (s_fb != 0);
    }

    if (fb) {
        // dense exact fallback via global scratch (rare: ~1e-3 of rows)
        float* frow = g_fbrow + (size_t)row * Ndim;
        for (int col = tid; col < Ndim; col += 256) {
            const float* wr = Wenc + (size_t)col * Kdim;
            float a = 0.f;
            for (int d = 0; d < Kdim; d += 4) {
                float4 w = *(const float4*)(wr + d);
                a = fmaf(s_x[d], w.x, a);     a = fmaf(s_x[d + 1], w.y, a);
                a = fmaf(s_x[d + 2], w.z, a); a = fmaf(s_x[d + 3], w.w, a);
            }
            frow[col] = fmaxf(a + __ldg(b_enc + col), 0.f);
        }
        __syncthreads();
        for (int it = 0; it < SAEK; it++) {
            float bv = -1e30f; int bi = 0x7FFFFFFF;
            for (int i = tid; i < Ndim; i += 256) {
                float v = frow[i];
                if (v > bv || (v == bv && i < bi)) { bv = v; bi = i; }
            }
#pragma unroll
            for (int o = 16; o; o >>= 1) {
                float ov = __shfl_down_sync(0xFFFFFFFFu, bv, o);
                int   oi = __shfl_down_sync(0xFFFFFFFFu, bi, o);
                if (ov > bv || (ov == bv && oi < bi)) { bv = ov; bi = oi; }
            }
            if (lane == 0) { s_rv[wid] = bv; s_ri[wid] = bi; }
            __syncthreads();
            if (tid == 0) {
                float wv = s_rv[0]; int wi = s_ri[0];
#pragma unroll
                for (int j = 1; j < 8; j++)
                    if (s_rv[j] > wv || (s_rv[j] == wv && s_ri[j] < wi)) { wv = s_rv[j]; wi = s_ri[j]; }
                s_sel_v[it] = wv; s_sel_i[it] = wi;
                frow[wi] = -1e30f;
            }
            __syncthreads();
        }
    }

    // fused decode
    const int d = tid;
    float acc = __ldg(b_dec + d);
#pragma unroll
    for (int j = 0; j < SAEK; j++)
        acc = fmaf(s_sel_v[j], __ldg(Wdec + (size_t)s_sel_i[j] * Kdim + d), acc);
    out[(size_t)row * Kdim + d] = acc;
}

// ---------------------------------------------------------------------------
extern "C" void kernel_launch(void* const* d_in, const int* in_sizes, int n_in,
                              void* d_out, int out_size)
{
    const float* x     = (const float*)d_in[0];
    const float* W_enc = (const float*)d_in[1];
    const float* b_enc = (const float*)d_in[2];
    const float* W_dec = (const float*)d_in[3];
    const float* b_dec = (const float*)d_in[4];
    float* out = (float*)d_out;

    static bool attr = false;
    if (!attr) {
        cudaFuncSetAttribute(screen_gemm_s8, cudaFuncAttributeMaxDynamicSharedMemorySize,
                             3 * STAGE8);
        attr = true;
    }

    stats_kernel<<<(Mdim + Ndim) / 8, 256>>>(x, W_enc, b_dec);
    prep_pack_s8<<<1024, 256>>>(x, W_enc, b_dec);

    dim3 g1(Ndim / 128, Mdim / 128);
    screen_gemm_s8<<<g1, 256, 3 * STAGE8>>>(b_enc);

    rescore_decode<<<Mdim, 256>>>(x, W_enc, b_enc, W_dec, b_dec, out);
}

// round 14
// speedup vs baseline: 1.4472x; 1.4472x over previous
#include <cuda_runtime.h>
#include <cstdint>

#define Mdim 8192
#define Ndim 8192
#define Kdim 256
#define SAEK 32
#define CCAP 512
#define TCOEF 0.1375f    // 2.2 sigma / 16 (R7-proven)
#define ECOEF 0.0100f    // gate margin (abs / ||x||)
#define WCOEF 0.0080f    // rescore window = 2*E, E = 0.004*rn (~5 sd of int8 dot err)

// ---------------- device scratch ----------------
__device__ uint32_t g_x8[(size_t)Mdim * Kdim / 4];   // int8 packed (x - b_dec)
__device__ uint32_t g_w8[(size_t)Ndim * Kdim / 4];   // int8 packed W_enc
__device__ float    g_rnorm[Mdim];
__device__ float    g_sx[Mdim],  g_isx[Mdim];
__device__ float    g_sw[Ndim],  g_isw[Ndim];
__device__ int      g_ccnt[Mdim];
__device__ float2   g_cand[(size_t)Mdim * CCAP];     // (screened val, col bits) 32 MB
__device__ float    g_fbrow[(size_t)Mdim * Ndim];    // dense-fallback scratch (cold)

// ---------------- portable PTX helpers ----------------
__device__ __forceinline__ uint32_t smem_u32(const void* p) {
    uint32_t a;
    asm("{ .reg .u64 t; cvta.to.shared.u64 t, %1; cvt.u32.u64 %0, t; }" : "=r"(a) : "l"(p));
    return a;
}
__device__ __forceinline__ void cp_async16(uint32_t s, const void* g) {
    asm volatile("cp.async.cg.shared.global [%0], [%1], 16;" :: "r"(s), "l"(g));
}
#define CP_COMMIT() asm volatile("cp.async.commit_group;" ::: "memory")

#define LDSM_X4(r0,r1,r2,r3,addr) \
    asm volatile("ldmatrix.sync.aligned.m8n8.x4.shared.b16 {%0,%1,%2,%3}, [%4];" \
        : "=r"(r0),"=r"(r1),"=r"(r2),"=r"(r3) : "r"(addr))
#define LDSM_X2(r0,r1,addr) \
    asm volatile("ldmatrix.sync.aligned.m8n8.x2.shared.b16 {%0,%1}, [%2];" \
        : "=r"(r0),"=r"(r1) : "r"(addr))
#define MMA_S8(d,a,b) \
    asm volatile("mma.sync.aligned.m16n8k32.row.col.s32.s8.s8.s32 " \
        "{%0,%1,%2,%3},{%4,%5,%6,%7},{%8,%9},{%0,%1,%2,%3};" \
        : "+r"((d)[0]),"+r"((d)[1]),"+r"((d)[2]),"+r"((d)[3]) \
        : "r"((a)[0]),"r"((a)[1]),"r"((a)[2]),"r"((a)[3]),"r"((b)[0]),"r"((b)[1]))

// ---------------------------------------------------------------------------
// Kernel: per-row stats + candidate-counter zeroing. One warp per row.
// ---------------------------------------------------------------------------
__global__ __launch_bounds__(256)
void stats_kernel(const float* __restrict__ x, const float* __restrict__ Wenc,
                  const float* __restrict__ b_dec)
{
    const int wid = threadIdx.x >> 5, lane = threadIdx.x & 31;
    const int row = blockIdx.x * 8 + wid;
    if (row < Mdim) {
        const float* xr = x + (size_t)row * Kdim + lane * 8;
        float s = 0.f, mx = 0.f;
#pragma unroll
        for (int j = 0; j < 8; j++) {
            float e = xr[j] - __ldg(b_dec + lane * 8 + j);
            s = fmaf(e, e, s);
            mx = fmaxf(mx, fabsf(e));
        }
#pragma unroll
        for (int o = 16; o; o >>= 1) {
            s  += __shfl_down_sync(0xFFFFFFFFu, s, o);
            mx = fmaxf(mx, __shfl_down_sync(0xFFFFFFFFu, mx, o));
        }
        if (lane == 0) {
            g_rnorm[row] = sqrtf(s);
            g_sx[row]  = mx * (1.f / 127.f);
            g_isx[row] = (mx > 0.f) ? (127.f / mx) : 0.f;
            g_ccnt[row] = 0;
        }
    } else {
        const int r = row - Mdim;
        const float* wr = Wenc + (size_t)r * Kdim + lane * 8;
        float mx = 0.f;
#pragma unroll
        for (int j = 0; j < 8; j++) mx = fmaxf(mx, fabsf(wr[j]));
#pragma unroll
        for (int o = 16; o; o >>= 1) mx = fmaxf(mx, __shfl_down_sync(0xFFFFFFFFu, mx, o));
        if (lane == 0) {
            g_sw[r]  = mx * (1.f / 127.f);
            g_isw[r] = (mx > 0.f) ? (127.f / mx) : 0.f;
        }
    }
}

// ---------------------------------------------------------------------------
// Kernel: quantize (x - b_dec) and W_enc to int8 (16 elements / thread)
// ---------------------------------------------------------------------------
__device__ __forceinline__ uint32_t q4(const float* v, float inv) {
    int q0 = max(-127, min(127, __float2int_rn(v[0] * inv)));
    int q1 = max(-127, min(127, __float2int_rn(v[1] * inv)));
    int q2 = max(-127, min(127, __float2int_rn(v[2] * inv)));
    int q3 = max(-127, min(127, __float2int_rn(v[3] * inv)));
    return (uint32_t)(q0 & 255) | ((uint32_t)(q1 & 255) << 8) |
           ((uint32_t)(q2 & 255) << 16) | ((uint32_t)(q3 & 255) << 24);
}

__global__ __launch_bounds__(256)
void prep_pack_s8(const float* __restrict__ x, const float* __restrict__ Wenc,
                  const float* __restrict__ b_dec)
{
    const size_t XT = (size_t)Mdim * Kdim / 16;
    size_t i = (size_t)blockIdx.x * 256 + threadIdx.x;
    float v[16];
    float inv;
    uint32_t* dst;
    if (i < XT) {
        const size_t base = i * 16;
        const int row = (int)(base >> 8);
        const int k = (int)(base & (Kdim - 1));
        inv = __ldg(g_isx + row);
#pragma unroll
        for (int j = 0; j < 16; j += 4) {
            float4 a = *(const float4*)(x + base + j);
            v[j]   = a.x - __ldg(b_dec + k + j);
            v[j+1] = a.y - __ldg(b_dec + k + j + 1);
            v[j+2] = a.z - __ldg(b_dec + k + j + 2);
            v[j+3] = a.w - __ldg(b_dec + k + j + 3);
        }
        dst = g_x8 + i * 4;
    } else {
        const size_t base = (i - XT) * 16;
        const int row = (int)(base >> 8);
        inv = __ldg(g_isw + row);
#pragma unroll
        for (int j = 0; j < 16; j += 4) {
            float4 a = *(const float4*)(Wenc + base + j);
            v[j] = a.x; v[j+1] = a.y; v[j+2] = a.z; v[j+3] = a.w;
        }
        dst = g_w8 + (i - XT) * 4;
    }
    uint4 o;
    o.x = q4(v + 0,  inv);
    o.y = q4(v + 4,  inv);
    o.z = q4(v + 8,  inv);
    o.w = q4(v + 12, inv);
    *(uint4*)dst = o;
}

// ---------------------------------------------------------------------------
// Kernel: int8 screening GEMM — EXACT R7 datapath (BK=32, X2 B loads).
// Epilogue stores (screened val, col) pairs.
// ---------------------------------------------------------------------------
#define SROW 48u
#define TILE8 (128u * SROW)      // 6144 B
#define STAGE8 (2u * TILE8)      // 12288 B

__global__ __launch_bounds__(256, 2)
void screen_gemm_s8(const float* __restrict__ b_enc)
{
    extern __shared__ char smc[];
    const uint32_t smb = smem_u32(smc);
    const int tid = threadIdx.x, lane = tid & 31, wid = tid >> 5;
    const int wm = wid & 1, wn = wid >> 1;
    const int m0 = blockIdx.y * 128, n0 = blockIdx.x * 128;

    int acc[4][4][4];
#pragma unroll
    for (int a = 0; a < 4; a++)
#pragma unroll
        for (int b = 0; b < 4; b++)
#pragma unroll
            for (int c = 0; c < 4; c++) acc[a][b][c] = 0;

    const int prow = tid >> 1;
    const int half = tid & 1;

    auto prefetch = [&](int c) {
        const uint32_t st = smb + (uint32_t)(c % 3) * STAGE8;
        const uint32_t da = st + (uint32_t)prow * SROW + (uint32_t)half * 16u;
        const char* ga = (const char*)g_x8 + (size_t)(m0 + prow) * Kdim + c * 32 + half * 16;
        const char* gb = (const char*)g_w8 + (size_t)(n0 + prow) * Kdim + c * 32 + half * 16;
        cp_async16(da,         ga);
        cp_async16(da + TILE8, gb);
        CP_COMMIT();
    };

    prefetch(0); prefetch(1);

    for (int c = 0; c < 8; c++) {
        if (c < 7) asm volatile("cp.async.wait_group 1;" ::: "memory");
        else       asm volatile("cp.async.wait_group 0;" ::: "memory");
        __syncthreads();
        if (c + 2 < 8) prefetch(c + 2);

        const uint32_t sA = smb + (uint32_t)(c % 3) * STAGE8;
        const uint32_t sB = sA + TILE8;

        uint32_t af[4][4], bf[4][2];
#pragma unroll
        for (int mt = 0; mt < 4; mt++) {
            const uint32_t ad = sA + (uint32_t)(wm * 64 + mt * 16 + (lane & 15)) * SROW
                              + (uint32_t)((lane >> 4) * 16);
            LDSM_X4(af[mt][0], af[mt][1], af[mt][2], af[mt][3], ad);
        }
#pragma unroll
        for (int nt = 0; nt < 4; nt++) {
            const uint32_t bd = sB + (uint32_t)(wn * 32 + nt * 8 + (lane & 7)) * SROW
                              + (uint32_t)(((lane >> 3) & 1) * 16);
            LDSM_X2(bf[nt][0], bf[nt][1], bd);
        }
#pragma unroll
        for (int mt = 0; mt < 4; mt++)
#pragma unroll
            for (int nt = 0; nt < 4; nt++)
                MMA_S8(acc[mt][nt], af[mt], bf[nt]);
    }

    // epilogue: dequant + threshold append (val, col)
#pragma unroll
    for (int mt = 0; mt < 4; mt++) {
        const int r0 = m0 + wm * 64 + mt * 16 + (lane >> 2);
        const int r1 = r0 + 8;
        const float sx0 = __ldg(g_sx + r0), sx1 = __ldg(g_sx + r1);
        const float T0 = TCOEF * __ldg(g_rnorm + r0);
        const float T1 = TCOEF * __ldg(g_rnorm + r1);
#pragma unroll
        for (int nt = 0; nt < 4; nt++) {
            const int c0 = n0 + wn * 32 + nt * 8 + 2 * (lane & 3);
            const float sw0 = __ldg(g_sw + c0), sw1 = __ldg(g_sw + c0 + 1);
            const float be0 = __ldg(b_enc + c0), be1 = __ldg(b_enc + c0 + 1);
            float v0 = (float)acc[mt][nt][0] * (sx0 * sw0) + be0;
            float v1 = (float)acc[mt][nt][1] * (sx0 * sw1) + be1;
            float v2 = (float)acc[mt][nt][2] * (sx1 * sw0) + be0;
            float v3 = (float)acc[mt][nt][3] * (sx1 * sw1) + be1;
            if (v0 >= T0) { int p = atomicAdd(&g_ccnt[r0], 1); if (p < CCAP) g_cand[(size_t)r0 * CCAP + p] = make_float2(v0, __int_as_float(c0)); }
            if (v1 >= T0) { int p = atomicAdd(&g_ccnt[r0], 1); if (p < CCAP) g_cand[(size_t)r0 * CCAP + p] = make_float2(v1, __int_as_float(c0 + 1)); }
            if (v2 >= T1) { int p = atomicAdd(&g_ccnt[r1], 1); if (p < CCAP) g_cand[(size_t)r1 * CCAP + p] = make_float2(v2, __int_as_float(c0)); }
            if (v3 >= T1) { int p = atomicAdd(&g_ccnt[r1], 1); if (p < CCAP) g_cand[(size_t)r1 * CCAP + p] = make_float2(v3, __int_as_float(c0 + 1)); }
        }
    }
}

// ---------------------------------------------------------------------------
// Kernel: two-stage rescore.
//  Stage 1: rank pass on SCREENED values -> S32 (32nd screened value).
//  Stage 2: exact fp32 rescore ONLY of candidates with screened >= S32 - 2E
//           (provable superset of the exact top-32 given pointwise |err|<=E).
//  Then rank top-32 on exact values + validity gate + fused decode.
// ---------------------------------------------------------------------------
__global__ __launch_bounds__(256)
void rescore_decode(const float* __restrict__ x, const float* __restrict__ Wenc,
                    const float* __restrict__ b_enc, const float* __restrict__ Wdec,
                    const float* __restrict__ b_dec, float* __restrict__ out)
{
    __shared__ float  s_x[Kdim];
    __shared__ __align__(16) float s_w[8][2][Kdim];   // 16 KB candidate buffers
    __shared__ float2 s_pair[CCAP];                   // 4 KB screened (val, col)
    __shared__ int    s_rcol[CCAP];                   // 2 KB window-compact cols
    __shared__ float  s_eval[CCAP];                   // 2 KB exact values
    __shared__ float  s_sel_v[SAEK];
    __shared__ int    s_sel_i[SAEK];
    __shared__ float  s_rv[8];
    __shared__ int    s_ri[8];
    __shared__ float  s_s32;
    __shared__ int    s_nr, s_fb;

    const int row = blockIdx.x;
    const int tid = threadIdx.x;
    const int wid = tid >> 5, lane = tid & 31;

    s_x[tid] = x[(size_t)row * Kdim + tid] - __ldg(b_dec + tid);
    if (tid == 0) { s_fb = 0; s_nr = 0; }
    __syncthreads();

    float xr[8];
#pragma unroll
    for (int j = 0; j < 8; j++) xr[j] = s_x[lane * 8 + j];

    const int n = g_ccnt[row];
    const float rn = g_rnorm[row];
    bool fb = (n < SAEK) || (n > CCAP);

    if (!fb) {
        for (int i = tid; i < n; i += 256) s_pair[i] = g_cand[(size_t)row * CCAP + i];
        __syncthreads();

        // Stage 1: rank pass on screened values -> S32 (rank 31, unique keys)
        for (int i = tid; i < n; i += 256) {
            const float vi = s_pair[i].x;
            const int   ci = __float_as_int(s_pair[i].y);
            int r = 0;
            for (int j = 0; j < n; j++) {
                const float vj = s_pair[j].x;
                r += (vj > vi) || (vj == vi && __float_as_int(s_pair[j].y) < ci);
            }
            if (r == SAEK - 1) s_s32 = vi;
        }
        __syncthreads();

        // window compaction (cap = CCAP => never overflows)
        const float W = s_s32 - WCOEF * rn;
        for (int i = tid; i < n; i += 256) {
            if (s_pair[i].x >= W) {
                int p = atomicAdd(&s_nr, 1);
                s_rcol[p] = __float_as_int(s_pair[i].y);
            }
        }
        __syncthreads();
        const int nr = s_nr;   // >= 32 by construction

        // Stage 2: exact fp32 dot per windowed candidate (R7 dbuf machinery)
        const uint32_t wb0 = smem_u32(&s_w[wid][0][0]) + (uint32_t)lane * 32u;
        const uint32_t wb1 = smem_u32(&s_w[wid][1][0]) + (uint32_t)lane * 32u;

        {
            const char* src = (const char*)(Wenc + (size_t)s_rcol[wid] * Kdim) + lane * 32;
            cp_async16(wb0,      src);
            cp_async16(wb0 + 16, src + 16);
        }
        CP_COMMIT();

        int buf = 0;
        for (int c = wid; c < nr; c += 8, buf ^= 1) {
            const int cn = c + 8;
            if (cn < nr) {
                const uint32_t d = buf ? wb0 : wb1;
                const char* src = (const char*)(Wenc + (size_t)s_rcol[cn] * Kdim) + lane * 32;
                cp_async16(d,      src);
                cp_async16(d + 16, src + 16);
            }
            CP_COMMIT();
            asm volatile("cp.async.wait_group 1;" ::: "memory");

            const float* wr = &s_w[wid][buf][lane * 8];
            float4 w0 = *(const float4*)wr;
            float4 w1 = *(const float4*)(wr + 4);
            float s = xr[0] * w0.x;
            s = fmaf(xr[1], w0.y, s); s = fmaf(xr[2], w0.z, s); s = fmaf(xr[3], w0.w, s);
            s = fmaf(xr[4], w1.x, s); s = fmaf(xr[5], w1.y, s); s = fmaf(xr[6], w1.z, s);
            s = fmaf(xr[7], w1.w, s);
#pragma unroll
            for (int o = 16; o; o >>= 1) s += __shfl_xor_sync(0xFFFFFFFFu, s, o);
            if (lane == 0) s_eval[c] = s + __ldg(b_enc + s_rcol[c]);
        }
        asm volatile("cp.async.wait_group 0;" ::: "memory");
        __syncthreads();

        // exact top-32 rank selection over the window (keys unique)
        for (int i = tid; i < nr; i += 256) {
            const float vi = s_eval[i];
            const int   ci = s_rcol[i];
            int r = 0;
            for (int j = 0; j < nr; j++) {
                const float vj = s_eval[j];
                r += (vj > vi) || (vj == vi && s_rcol[j] < ci);
            }
            if (r < SAEK) { s_sel_v[r] = vi; s_sel_i[r] = ci; }
        }
        __syncthreads();

        // validity gate (statistical backstop)
        if (tid == 0 && s_sel_v[SAEK - 1] < (TCOEF + ECOEF) * rn + 1e-6f) s_fb = 1;
        __syncthreads();
        fb = (s_fb != 0);
    }

    if (fb) {
        // dense exact fallback via global scratch (statistically never taken)
        float* frow = g_fbrow + (size_t)row * Ndim;
        for (int col = tid; col < Ndim; col += 256) {
            const float* wr = Wenc + (size_t)col * Kdim;
            float a = 0.f;
            for (int d = 0; d < Kdim; d += 4) {
                float4 w = *(const float4*)(wr + d);
                a = fmaf(s_x[d], w.x, a);     a = fmaf(s_x[d + 1], w.y, a);
                a = fmaf(s_x[d + 2], w.z, a); a = fmaf(s_x[d + 3], w.w, a);
            }
            frow[col] = fmaxf(a + __ldg(b_enc + col), 0.f);
        }
        __syncthreads();
        for (int it = 0; it < SAEK; it++) {
            float bv = -1e30f; int bi = 0x7FFFFFFF;
            for (int i = tid; i < Ndim; i += 256) {
                float v = frow[i];
                if (v > bv || (v == bv && i < bi)) { bv = v; bi = i; }
            }
#pragma unroll
            for (int o = 16; o; o >>= 1) {
                float ov = __shfl_down_sync(0xFFFFFFFFu, bv, o);
                int   oi = __shfl_down_sync(0xFFFFFFFFu, bi, o);
                if (ov > bv || (ov == bv && oi < bi)) { bv = ov; bi = oi; }
            }
            if (lane == 0) { s_rv[wid] = bv; s_ri[wid] = bi; }
            __syncthreads();
            if (tid == 0) {
                float wv = s_rv[0]; int wi = s_ri[0];
#pragma unroll
                for (int j = 1; j < 8; j++)
                    if (s_rv[j] > wv || (s_rv[j] == wv && s_ri[j] < wi)) { wv = s_rv[j]; wi = s_ri[j]; }
                s_sel_v[it] = wv; s_sel_i[it] = wi;
                frow[wi] = -1e30f;
            }
            __syncthreads();
        }
    }

    // fused decode
    const int d = tid;
    float acc = __ldg(b_dec + d);
#pragma unroll
    for (int j = 0; j < SAEK; j++)
        acc = fmaf(s_sel_v[j], __ldg(Wdec + (size_t)s_sel_i[j] * Kdim + d), acc);
    out[(size_t)row * Kdim + d] = acc;
}

// ---------------------------------------------------------------------------
extern "C" void kernel_launch(void* const* d_in, const int* in_sizes, int n_in,
                              void* d_out, int out_size)
{
    const float* x     = (const float*)d_in[0];
    const float* W_enc = (const float*)d_in[1];
    const float* b_enc = (const float*)d_in[2];
    const float* W_dec = (const float*)d_in[3];
    const float* b_dec = (const float*)d_in[4];
    float* out = (float*)d_out;

    static bool attr = false;
    if (!attr) {
        cudaFuncSetAttribute(screen_gemm_s8, cudaFuncAttributeMaxDynamicSharedMemorySize,
                             3 * STAGE8);
        attr = true;
    }

    stats_kernel<<<(Mdim + Ndim) / 8, 256>>>(x, W_enc, b_dec);
    prep_pack_s8<<<1024, 256>>>(x, W_enc, b_dec);

    dim3 g1(Ndim / 128, Mdim / 128);
    screen_gemm_s8<<<g1, 256, 3 * STAGE8>>>(b_enc);

    rescore_decode<<<Mdim, 256>>>(x, W_enc, b_enc, W_dec, b_dec, out);
}

// round 15
// speedup vs baseline: 1.4946x; 1.0327x over previous
#include <cuda_runtime.h>
#include <cstdint>

#define Mdim 8192
#define Ndim 8192
#define Kdim 256
#define SAEK 32
#define CCAP 512
#define TCOEF 0.1375f    // 2.2 sigma / 16 (R7-proven)
#define ECOEF 0.0100f    // gate margin (abs / ||x||)
#define WCOEF 0.0080f    // rescore window = 2*E (~5 sd of int8 dot err)

// ---------------- device scratch ----------------
__device__ uint32_t g_x8[(size_t)Mdim * Kdim / 4];   // int8 packed (x - b_dec)
__device__ uint32_t g_w8[(size_t)Ndim * Kdim / 4];   // int8 packed W_enc
__device__ float    g_rnorm[Mdim];
__device__ float    g_sx[Mdim],  g_isx[Mdim];
__device__ float    g_sw[Ndim],  g_isw[Ndim];
__device__ int      g_ccnt[Mdim];
__device__ float2   g_cand[(size_t)Mdim * CCAP];     // (screened val, col bits)
__device__ float    g_fbrow[(size_t)Mdim * Ndim];    // dense-fallback scratch (cold)

// ---------------- portable PTX helpers ----------------
__device__ __forceinline__ uint32_t smem_u32(const void* p) {
    uint32_t a;
    asm("{ .reg .u64 t; cvta.to.shared.u64 t, %1; cvt.u32.u64 %0, t; }" : "=r"(a) : "l"(p));
    return a;
}
__device__ __forceinline__ void cp_async16(uint32_t s, const void* g) {
    asm volatile("cp.async.cg.shared.global [%0], [%1], 16;" :: "r"(s), "l"(g));
}
#define CP_COMMIT() asm volatile("cp.async.commit_group;" ::: "memory")

#define LDSM_X4(r0,r1,r2,r3,addr) \
    asm volatile("ldmatrix.sync.aligned.m8n8.x4.shared.b16 {%0,%1,%2,%3}, [%4];" \
        : "=r"(r0),"=r"(r1),"=r"(r2),"=r"(r3) : "r"(addr))
#define LDSM_X2(r0,r1,addr) \
    asm volatile("ldmatrix.sync.aligned.m8n8.x2.shared.b16 {%0,%1}, [%2];" \
        : "=r"(r0),"=r"(r1) : "r"(addr))
#define MMA_S8(d,a,b) \
    asm volatile("mma.sync.aligned.m16n8k32.row.col.s32.s8.s8.s32 " \
        "{%0,%1,%2,%3},{%4,%5,%6,%7},{%8,%9},{%0,%1,%2,%3};" \
        : "+r"((d)[0]),"+r"((d)[1]),"+r"((d)[2]),"+r"((d)[3]) \
        : "r"((a)[0]),"r"((a)[1]),"r"((a)[2]),"r"((a)[3]),"r"((b)[0]),"r"((b)[1]))

// ---------------------------------------------------------------------------
// Kernel: per-row stats + candidate-counter zeroing. One warp per row.
// ---------------------------------------------------------------------------
__global__ __launch_bounds__(256)
void stats_kernel(const float* __restrict__ x, const float* __restrict__ Wenc,
                  const float* __restrict__ b_dec)
{
    const int wid = threadIdx.x >> 5, lane = threadIdx.x & 31;
    const int row = blockIdx.x * 8 + wid;
    if (row < Mdim) {
        const float* xr = x + (size_t)row * Kdim + lane * 8;
        float s = 0.f, mx = 0.f;
#pragma unroll
        for (int j = 0; j < 8; j++) {
            float e = xr[j] - __ldg(b_dec + lane * 8 + j);
            s = fmaf(e, e, s);
            mx = fmaxf(mx, fabsf(e));
        }
#pragma unroll
        for (int o = 16; o; o >>= 1) {
            s  += __shfl_down_sync(0xFFFFFFFFu, s, o);
            mx = fmaxf(mx, __shfl_down_sync(0xFFFFFFFFu, mx, o));
        }
        if (lane == 0) {
            g_rnorm[row] = sqrtf(s);
            g_sx[row]  = mx * (1.f / 127.f);
            g_isx[row] = (mx > 0.f) ? (127.f / mx) : 0.f;
            g_ccnt[row] = 0;
        }
    } else {
        const int r = row - Mdim;
        const float* wr = Wenc + (size_t)r * Kdim + lane * 8;
        float mx = 0.f;
#pragma unroll
        for (int j = 0; j < 8; j++) mx = fmaxf(mx, fabsf(wr[j]));
#pragma unroll
        for (int o = 16; o; o >>= 1) mx = fmaxf(mx, __shfl_down_sync(0xFFFFFFFFu, mx, o));
        if (lane == 0) {
            g_sw[r]  = mx * (1.f / 127.f);
            g_isw[r] = (mx > 0.f) ? (127.f / mx) : 0.f;
        }
    }
}

// ---------------------------------------------------------------------------
// Kernel: quantize (x - b_dec) and W_enc to int8 (16 elements / thread)
// ---------------------------------------------------------------------------
__device__ __forceinline__ uint32_t q4(const float* v, float inv) {
    int q0 = max(-127, min(127, __float2int_rn(v[0] * inv)));
    int q1 = max(-127, min(127, __float2int_rn(v[1] * inv)));
    int q2 = max(-127, min(127, __float2int_rn(v[2] * inv)));
    int q3 = max(-127, min(127, __float2int_rn(v[3] * inv)));
    return (uint32_t)(q0 & 255) | ((uint32_t)(q1 & 255) << 8) |
           ((uint32_t)(q2 & 255) << 16) | ((uint32_t)(q3 & 255) << 24);
}

__global__ __launch_bounds__(256)
void prep_pack_s8(const float* __restrict__ x, const float* __restrict__ Wenc,
                  const float* __restrict__ b_dec)
{
    const size_t XT = (size_t)Mdim * Kdim / 16;
    size_t i = (size_t)blockIdx.x * 256 + threadIdx.x;
    float v[16];
    float inv;
    uint32_t* dst;
    if (i < XT) {
        const size_t base = i * 16;
        const int row = (int)(base >> 8);
        const int k = (int)(base & (Kdim - 1));
        inv = __ldg(g_isx + row);
#pragma unroll
        for (int j = 0; j < 16; j += 4) {
            float4 a = *(const float4*)(x + base + j);
            v[j]   = a.x - __ldg(b_dec + k + j);
            v[j+1] = a.y - __ldg(b_dec + k + j + 1);
            v[j+2] = a.z - __ldg(b_dec + k + j + 2);
            v[j+3] = a.w - __ldg(b_dec + k + j + 3);
        }
        dst = g_x8 + i * 4;
    } else {
        const size_t base = (i - XT) * 16;
        const int row = (int)(base >> 8);
        inv = __ldg(g_isw + row);
#pragma unroll
        for (int j = 0; j < 16; j += 4) {
            float4 a = *(const float4*)(Wenc + base + j);
            v[j] = a.x; v[j+1] = a.y; v[j+2] = a.z; v[j+3] = a.w;
        }
        dst = g_w8 + (i - XT) * 4;
    }
    uint4 o;
    o.x = q4(v + 0,  inv);
    o.y = q4(v + 4,  inv);
    o.z = q4(v + 8,  inv);
    o.w = q4(v + 12, inv);
    *(uint4*)dst = o;
}

// ---------------------------------------------------------------------------
// Kernel: int8 screening GEMM — 512 threads, 16 warps, warp tile 32x32.
// BK=32, 3-stage cp.async, R7-proven X4(A)/X2(B) fragment loads.
// ---------------------------------------------------------------------------
#define SROW 48u
#define TILE8 (128u * SROW)      // 6144 B
#define STAGE8 (2u * TILE8)      // 12288 B

__global__ __launch_bounds__(512, 2)
void screen_gemm_s8(const float* __restrict__ b_enc)
{
    extern __shared__ char smc[];
    const uint32_t smb = smem_u32(smc);
    const int tid = threadIdx.x, lane = tid & 31, wid = tid >> 5;
    const int wm = wid & 3, wn = wid >> 2;       // 4x4 warp grid, 32x32 tiles
    const int m0 = blockIdx.y * 128, n0 = blockIdx.x * 128;

    int acc[2][4][4];
#pragma unroll
    for (int a = 0; a < 2; a++)
#pragma unroll
        for (int b = 0; b < 4; b++)
#pragma unroll
            for (int c = 0; c < 4; c++) acc[a][b][c] = 0;

    // prefetch: 512 threads cover A(256 units) + B(256 units), 1 cp16 each
    const int pten = tid >> 8;           // 0 = A, 1 = B
    const int prow = (tid & 255) >> 1;
    const int half = tid & 1;

    auto prefetch = [&](int c) {
        const uint32_t st = smb + (uint32_t)(c % 3) * STAGE8;
        const uint32_t da = st + (uint32_t)pten * TILE8
                          + (uint32_t)prow * SROW + (uint32_t)half * 16u;
        const char* g = pten
            ? (const char*)g_w8 + (size_t)(n0 + prow) * Kdim + c * 32 + half * 16
            : (const char*)g_x8 + (size_t)(m0 + prow) * Kdim + c * 32 + half * 16;
        cp_async16(da, g);
        CP_COMMIT();
    };

    prefetch(0); prefetch(1);

    for (int c = 0; c < 8; c++) {
        if (c < 7) asm volatile("cp.async.wait_group 1;" ::: "memory");
        else       asm volatile("cp.async.wait_group 0;" ::: "memory");
        __syncthreads();
        if (c + 2 < 8) prefetch(c + 2);

        const uint32_t sA = smb + (uint32_t)(c % 3) * STAGE8;
        const uint32_t sB = sA + TILE8;

        uint32_t af[2][4], bf[4][2];
#pragma unroll
        for (int mt = 0; mt < 2; mt++) {
            const uint32_t ad = sA + (uint32_t)(wm * 32 + mt * 16 + (lane & 15)) * SROW
                              + (uint32_t)((lane >> 4) * 16);
            LDSM_X4(af[mt][0], af[mt][1], af[mt][2], af[mt][3], ad);
        }
#pragma unroll
        for (int nt = 0; nt < 4; nt++) {
            const uint32_t bd = sB + (uint32_t)(wn * 32 + nt * 8 + (lane & 7)) * SROW
                              + (uint32_t)(((lane >> 3) & 1) * 16);
            LDSM_X2(bf[nt][0], bf[nt][1], bd);
        }
#pragma unroll
        for (int mt = 0; mt < 2; mt++)
#pragma unroll
            for (int nt = 0; nt < 4; nt++)
                MMA_S8(acc[mt][nt], af[mt], bf[nt]);
    }

    // epilogue: dequant + threshold append (val, col)
#pragma unroll
    for (int mt = 0; mt < 2; mt++) {
        const int r0 = m0 + wm * 32 + mt * 16 + (lane >> 2);
        const int r1 = r0 + 8;
        const float sx0 = __ldg(g_sx + r0), sx1 = __ldg(g_sx + r1);
        const float T0 = TCOEF * __ldg(g_rnorm + r0);
        const float T1 = TCOEF * __ldg(g_rnorm + r1);
#pragma unroll
        for (int nt = 0; nt < 4; nt++) {
            const int c0 = n0 + wn * 32 + nt * 8 + 2 * (lane & 3);
            const float sw0 = __ldg(g_sw + c0), sw1 = __ldg(g_sw + c0 + 1);
            const float be0 = __ldg(b_enc + c0), be1 = __ldg(b_enc + c0 + 1);
            float v0 = (float)acc[mt][nt][0] * (sx0 * sw0) + be0;
            float v1 = (float)acc[mt][nt][1] * (sx0 * sw1) + be1;
            float v2 = (float)acc[mt][nt][2] * (sx1 * sw0) + be0;
            float v3 = (float)acc[mt][nt][3] * (sx1 * sw1) + be1;
            if (v0 >= T0) { int p = atomicAdd(&g_ccnt[r0], 1); if (p < CCAP) g_cand[(size_t)r0 * CCAP + p] = make_float2(v0, __int_as_float(c0)); }
            if (v1 >= T0) { int p = atomicAdd(&g_ccnt[r0], 1); if (p < CCAP) g_cand[(size_t)r0 * CCAP + p] = make_float2(v1, __int_as_float(c0 + 1)); }
            if (v2 >= T1) { int p = atomicAdd(&g_ccnt[r1], 1); if (p < CCAP) g_cand[(size_t)r1 * CCAP + p] = make_float2(v2, __int_as_float(c0)); }
            if (v3 >= T1) { int p = atomicAdd(&g_ccnt[r1], 1); if (p < CCAP) g_cand[(size_t)r1 * CCAP + p] = make_float2(v3, __int_as_float(c0 + 1)); }
        }
    }
}

// ---------------------------------------------------------------------------
// Kernel: two-stage rescore (R14, unchanged).
// ---------------------------------------------------------------------------
__global__ __launch_bounds__(256)
void rescore_decode(const float* __restrict__ x, const float* __restrict__ Wenc,
                    const float* __restrict__ b_enc, const float* __restrict__ Wdec,
                    const float* __restrict__ b_dec, float* __restrict__ out)
{
    __shared__ float  s_x[Kdim];
    __shared__ __align__(16) float s_w[8][2][Kdim];   // 16 KB candidate buffers
    __shared__ float2 s_pair[CCAP];
    __shared__ int    s_rcol[CCAP];
    __shared__ float  s_eval[CCAP];
    __shared__ float  s_sel_v[SAEK];
    __shared__ int    s_sel_i[SAEK];
    __shared__ float  s_rv[8];
    __shared__ int    s_ri[8];
    __shared__ float  s_s32;
    __shared__ int    s_nr, s_fb;

    const int row = blockIdx.x;
    const int tid = threadIdx.x;
    const int wid = tid >> 5, lane = tid & 31;

    s_x[tid] = x[(size_t)row * Kdim + tid] - __ldg(b_dec + tid);
    if (tid == 0) { s_fb = 0; s_nr = 0; }
    __syncthreads();

    float xr[8];
#pragma unroll
    for (int j = 0; j < 8; j++) xr[j] = s_x[lane * 8 + j];

    const int n = g_ccnt[row];
    const float rn = g_rnorm[row];
    bool fb = (n < SAEK) || (n > CCAP);

    if (!fb) {
        for (int i = tid; i < n; i += 256) s_pair[i] = g_cand[(size_t)row * CCAP + i];
        __syncthreads();

        // Stage 1: rank pass on screened values -> S32 (rank 31, unique keys)
        for (int i = tid; i < n; i += 256) {
            const float vi = s_pair[i].x;
            const int   ci = __float_as_int(s_pair[i].y);
            int r = 0;
            for (int j = 0; j < n; j++) {
                const float vj = s_pair[j].x;
                r += (vj > vi) || (vj == vi && __float_as_int(s_pair[j].y) < ci);
            }
            if (r == SAEK - 1) s_s32 = vi;
        }
        __syncthreads();

        // window compaction (cap = CCAP => never overflows)
        const float W = s_s32 - WCOEF * rn;
        for (int i = tid; i < n; i += 256) {
            if (s_pair[i].x >= W) {
                int p = atomicAdd(&s_nr, 1);
                s_rcol[p] = __float_as_int(s_pair[i].y);
            }
        }
        __syncthreads();
        const int nr = s_nr;

        // Stage 2: exact fp32 dot per windowed candidate
        const uint32_t wb0 = smem_u32(&s_w[wid][0][0]) + (uint32_t)lane * 32u;
        const uint32_t wb1 = smem_u32(&s_w[wid][1][0]) + (uint32_t)lane * 32u;

        {
            const char* src = (const char*)(Wenc + (size_t)s_rcol[wid] * Kdim) + lane * 32;
            cp_async16(wb0,      src);
            cp_async16(wb0 + 16, src + 16);
        }
        CP_COMMIT();

        int buf = 0;
        for (int c = wid; c < nr; c += 8, buf ^= 1) {
            const int cn = c + 8;
            if (cn < nr) {
                const uint32_t d = buf ? wb0 : wb1;
                const char* src = (const char*)(Wenc + (size_t)s_rcol[cn] * Kdim) + lane * 32;
                cp_async16(d,      src);
                cp_async16(d + 16, src + 16);
            }
            CP_COMMIT();
            asm volatile("cp.async.wait_group 1;" ::: "memory");

            const float* wr = &s_w[wid][buf][lane * 8];
            float4 w0 = *(const float4*)wr;
            float4 w1 = *(const float4*)(wr + 4);
            float s = xr[0] * w0.x;
            s = fmaf(xr[1], w0.y, s); s = fmaf(xr[2], w0.z, s); s = fmaf(xr[3], w0.w, s);
            s = fmaf(xr[4], w1.x, s); s = fmaf(xr[5], w1.y, s); s = fmaf(xr[6], w1.z, s);
            s = fmaf(xr[7], w1.w, s);
#pragma unroll
            for (int o = 16; o; o >>= 1) s += __shfl_xor_sync(0xFFFFFFFFu, s, o);
            if (lane == 0) s_eval[c] = s + __ldg(b_enc + s_rcol[c]);
        }
        asm volatile("cp.async.wait_group 0;" ::: "memory");
        __syncthreads();

        // exact top-32 rank selection over the window (keys unique)
        for (int i = tid; i < nr; i += 256) {
            const float vi = s_eval[i];
            const int   ci = s_rcol[i];
            int r = 0;
            for (int j = 0; j < nr; j++) {
                const float vj = s_eval[j];
                r += (vj > vi) || (vj == vi && s_rcol[j] < ci);
            }
            if (r < SAEK) { s_sel_v[r] = vi; s_sel_i[r] = ci; }
        }
        __syncthreads();

        // validity gate (statistical backstop)
        if (tid == 0 && s_sel_v[SAEK - 1] < (TCOEF + ECOEF) * rn + 1e-6f) s_fb = 1;
        __syncthreads();
        fb = (s_fb != 0);
    }

    if (fb) {
        // dense exact fallback via global scratch (statistically never taken)
        float* frow = g_fbrow + (size_t)row * Ndim;
        for (int col = tid; col < Ndim; col += 256) {
            const float* wr = Wenc + (size_t)col * Kdim;
            float a = 0.f;
            for (int d = 0; d < Kdim; d += 4) {
                float4 w = *(const float4*)(wr + d);
                a = fmaf(s_x[d], w.x, a);     a = fmaf(s_x[d + 1], w.y, a);
                a = fmaf(s_x[d + 2], w.z, a); a = fmaf(s_x[d + 3], w.w, a);
            }
            frow[col] = fmaxf(a + __ldg(b_enc + col), 0.f);
        }
        __syncthreads();
        for (int it = 0; it < SAEK; it++) {
            float bv = -1e30f; int bi = 0x7FFFFFFF;
            for (int i = tid; i < Ndim; i += 256) {
                float v = frow[i];
                if (v > bv || (v == bv && i < bi)) { bv = v; bi = i; }
            }
#pragma unroll
            for (int o = 16; o; o >>= 1) {
                float ov = __shfl_down_sync(0xFFFFFFFFu, bv, o);
                int   oi = __shfl_down_sync(0xFFFFFFFFu, bi, o);
                if (ov > bv || (ov == bv && oi < bi)) { bv = ov; bi = oi; }
            }
            if (lane == 0) { s_rv[wid] = bv; s_ri[wid] = bi; }
            __syncthreads();
            if (tid == 0) {
                float wv = s_rv[0]; int wi = s_ri[0];
#pragma unroll
                for (int j = 1; j < 8; j++)
                    if (s_rv[j] > wv || (s_rv[j] == wv && s_ri[j] < wi)) { wv = s_rv[j]; wi = s_ri[j]; }
                s_sel_v[it] = wv; s_sel_i[it] = wi;
                frow[wi] = -1e30f;
            }
            __syncthreads();
        }
    }

    // fused decode
    const int d = tid;
    float acc = __ldg(b_dec + d);
#pragma unroll
    for (int j = 0; j < SAEK; j++)
        acc = fmaf(s_sel_v[j], __ldg(Wdec + (size_t)s_sel_i[j] * Kdim + d), acc);
    out[(size_t)row * Kdim + d] = acc;
}

// ---------------------------------------------------------------------------
extern "C" void kernel_launch(void* const* d_in, const int* in_sizes, int n_in,
                              void* d_out, int out_size)
{
    const float* x     = (const float*)d_in[0];
    const float* W_enc = (const float*)d_in[1];
    const float* b_enc = (const float*)d_in[2];
    const float* W_dec = (const float*)d_in[3];
    const float* b_dec = (const float*)d_in[4];
    float* out = (float*)d_out;

    static bool attr = false;
    if (!attr) {
        cudaFuncSetAttribute(screen_gemm_s8, cudaFuncAttributeMaxDynamicSharedMemorySize,
                             3 * STAGE8);
        attr = true;
    }

    stats_kernel<<<(Mdim + Ndim) / 8, 256>>>(x, W_enc, b_dec);
    prep_pack_s8<<<1024, 256>>>(x, W_enc, b_dec);

    dim3 g1(Ndim / 128, Mdim / 128);
    screen_gemm_s8<<<g1, 512, 3 * STAGE8>>>(b_enc);

    rescore_decode<<<Mdim, 256>>>(x, W_enc, b_enc, W_dec, b_dec, out);
}